// round 2
// baseline (speedup 1.0000x reference)
#include <cuda_runtime.h>
#include <cuda_bf16.h>
#include <mma.h>

using namespace nvcuda;

#define N_NODES 100000
#define N_EDGES 1600000
#define SZ_IN   128
#define DIM_I   1024

// Scratch: node-transformed features y = relu(x @ W^T + b), and scatter-max result hn.
__device__ float g_y[N_NODES * SZ_IN];   // 51.2 MB
__device__ float g_hn[N_NODES * SZ_IN];  // 51.2 MB

// ---------------------------------------------------------------------------
// helpers
// ---------------------------------------------------------------------------
template <typename Frag>
__device__ __forceinline__ void frag_to_tf32(Frag& f) {
#pragma unroll
    for (int i = 0; i < f.num_elements; i++) f.x[i] = wmma::__float_to_tf32(f.x[i]);
}

// ---------------------------------------------------------------------------
// Kernel 1: y = relu(x @ agg_W^T + agg_b)   [N_NODES x 128]
// Each warp computes a 16x128 tile. 100000 % 16 == 0.
// ---------------------------------------------------------------------------
__global__ void __launch_bounds__(128) node_transform_kernel(
    const float* __restrict__ x,
    const float* __restrict__ W,      // [128,128] row-major (out,in)
    const float* __restrict__ bias)   // [128]
{
    const int warp = threadIdx.x >> 5;
    const int lane = threadIdx.x & 31;
    const int warp_tile = blockIdx.x * 4 + warp;
    if (warp_tile >= N_NODES / 16) return;
    const int m0 = warp_tile * 16;

    wmma::fragment<wmma::accumulator, 16, 16, 8, float> acc[8];
#pragma unroll
    for (int n = 0; n < 8; n++) wmma::fill_fragment(acc[n], 0.0f);

#pragma unroll 4
    for (int kk = 0; kk < SZ_IN / 8; kk++) {
        const int k0 = kk * 8;
        wmma::fragment<wmma::matrix_a, 16, 16, 8, wmma::precision::tf32, wmma::row_major> a;
        wmma::load_matrix_sync(a, x + (size_t)m0 * SZ_IN + k0, SZ_IN);
        frag_to_tf32(a);
#pragma unroll
        for (int n = 0; n < 8; n++) {
            // B[k][n] = W[n][k]  -> col-major view of W, ld = 128
            wmma::fragment<wmma::matrix_b, 16, 16, 8, wmma::precision::tf32, wmma::col_major> b;
            wmma::load_matrix_sync(b, W + (size_t)(n * 16) * SZ_IN + k0, SZ_IN);
            frag_to_tf32(b);
            wmma::mma_sync(acc[n], a, b, acc[n]);
        }
    }

    // stage through smem to apply per-column bias + relu
    __shared__ float s[4][16 * SZ_IN];
#pragma unroll
    for (int n = 0; n < 8; n++)
        wmma::store_matrix_sync(&s[warp][n * 16], acc[n], SZ_IN, wmma::mem_row_major);

    float* out = g_y + (size_t)m0 * SZ_IN;
#pragma unroll
    for (int i = lane; i < 16 * SZ_IN; i += 32) {
        const int col = i & (SZ_IN - 1);
        float v = s[warp][i] + bias[col];
        out[i] = v > 0.0f ? v : 0.0f;
    }
}

// ---------------------------------------------------------------------------
// Kernel 2: zero hn
// ---------------------------------------------------------------------------
__global__ void __launch_bounds__(256) zero_hn_kernel() {
    const size_t total4 = (size_t)N_NODES * SZ_IN / 4;
    float4 z = make_float4(0.f, 0.f, 0.f, 0.f);
    for (size_t i = (size_t)blockIdx.x * blockDim.x + threadIdx.x; i < total4;
         i += (size_t)gridDim.x * blockDim.x)
        reinterpret_cast<float4*>(g_hn)[i] = z;
}

// ---------------------------------------------------------------------------
// Kernel 3: scatter-max.  One warp per edge: hn[u] = max(hn[u], y[v]).
// edge_index is INT32 (JAX x64 disabled downcasts int64 -> int32).
// All values >= 0 so int atomicMax on float bits is exact.
// ---------------------------------------------------------------------------
__global__ void __launch_bounds__(256) scatter_max_kernel(
    const int* __restrict__ edge_index, int num_edges)
{
    const int e = (blockIdx.x * blockDim.x + threadIdx.x) >> 5;
    const int lane = threadIdx.x & 31;
    if (e >= num_edges) return;
    const int u = edge_index[e];
    const int v = edge_index[num_edges + e];
    if ((unsigned)u >= N_NODES || (unsigned)v >= N_NODES) return;  // insurance, never taken
    const float* src = g_y + (size_t)v * SZ_IN;
    int* dst = reinterpret_cast<int*>(g_hn + (size_t)u * SZ_IN);
#pragma unroll
    for (int j = 0; j < 4; j++) {
        const int f = lane + 32 * j;
        atomicMax(&dst[f], __float_as_int(src[f]));
    }
}

// ---------------------------------------------------------------------------
// Kernel 4: h = relu(concat(x, hn) @ lin_W^T)   [N_NODES x 1024]
// Block = 8 warps sharing one n-tile of 128, each warp a distinct 16-row
// m-tile. K = 256 split: k<128 from x, k>=128 from hn.
// ---------------------------------------------------------------------------
__global__ void __launch_bounds__(256) output_gemm_kernel(
    const float* __restrict__ x,
    const float* __restrict__ lw,    // [1024, 256] row-major (out,in)
    float* __restrict__ out)
{
    const int warp = threadIdx.x >> 5;
    const int m_tile = blockIdx.x * 8 + warp;
    if (m_tile >= N_NODES / 16) return;
    const int m0 = m_tile * 16;
    const int n0 = blockIdx.y * 128;

    wmma::fragment<wmma::accumulator, 16, 16, 8, float> acc[8];
#pragma unroll
    for (int j = 0; j < 8; j++) wmma::fill_fragment(acc[j], 0.0f);

#pragma unroll 4
    for (int kk = 0; kk < 32; kk++) {
        const int k0 = kk * 8;
        const float* aptr = (k0 < SZ_IN)
            ? (x + (size_t)m0 * SZ_IN + k0)
            : (g_hn + (size_t)m0 * SZ_IN + (k0 - SZ_IN));
        wmma::fragment<wmma::matrix_a, 16, 16, 8, wmma::precision::tf32, wmma::row_major> a;
        wmma::load_matrix_sync(a, aptr, SZ_IN);
        frag_to_tf32(a);
#pragma unroll
        for (int j = 0; j < 8; j++) {
            wmma::fragment<wmma::matrix_b, 16, 16, 8, wmma::precision::tf32, wmma::col_major> b;
            wmma::load_matrix_sync(b, lw + (size_t)(n0 + j * 16) * 256 + k0, 256);
            frag_to_tf32(b);
            wmma::mma_sync(acc[j], a, b, acc[j]);
        }
    }

#pragma unroll
    for (int j = 0; j < 8; j++) {
#pragma unroll
        for (int i = 0; i < acc[j].num_elements; i++)
            acc[j].x[i] = fmaxf(acc[j].x[i], 0.0f);
        wmma::store_matrix_sync(out + (size_t)m0 * DIM_I + n0 + j * 16, acc[j],
                                DIM_I, wmma::mem_row_major);
    }
}

// ---------------------------------------------------------------------------
extern "C" void kernel_launch(void* const* d_in, const int* in_sizes, int n_in,
                              void* d_out, int out_size) {
    const float* x     = (const float*)d_in[0];
    const int*   eidx  = (const int*)d_in[1];      // int32! (JAX default x64 disabled)
    const float* agg_W = (const float*)d_in[2];
    const float* agg_b = (const float*)d_in[3];
    const float* lin_W = (const float*)d_in[4];
    float*       out   = (float*)d_out;

    const int num_edges = in_sizes[1] / 2;

    // 1) per-node transform (16x cheaper than per-edge)
    {
        const int warp_tiles = N_NODES / 16;            // 6250
        const int blocks = (warp_tiles + 3) / 4;        // 1563
        node_transform_kernel<<<blocks, 128>>>(x, agg_W, agg_b);
    }
    // 2) zero hn
    zero_hn_kernel<<<6400, 256>>>();
    // 3) scatter-max over edges
    {
        const long long total_threads = (long long)num_edges * 32;
        const int blocks = (int)((total_threads + 255) / 256); // 200000
        scatter_max_kernel<<<blocks, 256>>>(eidx, num_edges);
    }
    // 4) output GEMM + relu
    {
        const int m_tiles = N_NODES / 16;               // 6250
        dim3 grid((m_tiles + 7) / 8, DIM_I / 128);      // (782, 8)
        output_gemm_kernel<<<grid, 256>>>(x, lin_W, out);
    }
}

// round 4
// speedup vs baseline: 2.1523x; 2.1523x over previous
#include <cuda_runtime.h>
#include <cuda_bf16.h>
#include <mma.h>

using namespace nvcuda;

#define N_NODES 100000
#define N_EDGES 1600000
#define SZ_IN   128
#define DIM_I   1024

#define KC  32      // K chunk staged per iteration
#define LDP 40      // padded smem leading dim (160B: mult of 16B and of 8 elems)
#define LDC 132     // padded staging ld for kernel-1 epilogue (528B, mult of 16B)

// Scratch: node-transformed features y = relu(x @ W^T + b), and scatter-max result hn.
__device__ float g_y[N_NODES * SZ_IN];   // 51.2 MB
__device__ float g_hn[N_NODES * SZ_IN];  // 51.2 MB

__device__ __forceinline__ float4 to_tf32x4(float4 v) {
    v.x = wmma::__float_to_tf32(v.x);
    v.y = wmma::__float_to_tf32(v.y);
    v.z = wmma::__float_to_tf32(v.z);
    v.w = wmma::__float_to_tf32(v.w);
    return v;
}

// ---------------------------------------------------------------------------
// Kernel 1: y = relu(x @ agg_W^T + agg_b)   [100000 x 128], K=128
// Tiled: block = 128(M) x 128(N), 8 warps each 64x32, smem-staged A and W.
// ---------------------------------------------------------------------------
__global__ void __launch_bounds__(256) node_transform_kernel(
    const float* __restrict__ x,
    const float* __restrict__ W,      // [128,128] row-major (out,in)
    const float* __restrict__ bias)   // [128]
{
    __shared__ float As[128 * LDP];
    __shared__ float Bs[128 * LDP];
    __shared__ float Cs[128 * LDC];

    const int tid  = threadIdx.x;
    const int warp = tid >> 5;
    const int m0   = blockIdx.x * 128;
    const int wm   = warp >> 2;   // 0..1
    const int wn   = warp & 3;    // 0..3

    wmma::fragment<wmma::accumulator, 16, 16, 8, float> acc[4][2];
#pragma unroll
    for (int i = 0; i < 4; i++)
#pragma unroll
        for (int j = 0; j < 2; j++) wmma::fill_fragment(acc[i][j], 0.0f);

    for (int kc = 0; kc < SZ_IN; kc += KC) {
        // stage A chunk [128m x 32k] and W chunk [128n x 32k]
#pragma unroll
        for (int it = 0; it < 4; it++) {
            const int idx = it * 256 + tid;   // 0..1023
            const int r  = idx >> 3;          // row / n within tile
            const int kq = idx & 7;           // which float4 along k
            const int row = m0 + r;
            float4 a = make_float4(0.f, 0.f, 0.f, 0.f);
            if (row < N_NODES)
                a = *reinterpret_cast<const float4*>(x + (size_t)row * SZ_IN + kc + kq * 4);
            *reinterpret_cast<float4*>(&As[r * LDP + kq * 4]) = to_tf32x4(a);
            float4 b = *reinterpret_cast<const float4*>(W + (size_t)r * SZ_IN + kc + kq * 4);
            *reinterpret_cast<float4*>(&Bs[r * LDP + kq * 4]) = to_tf32x4(b);
        }
        __syncthreads();
#pragma unroll
        for (int ks = 0; ks < KC / 8; ks++) {
            wmma::fragment<wmma::matrix_a, 16, 16, 8, wmma::precision::tf32, wmma::row_major> a[4];
#pragma unroll
            for (int i = 0; i < 4; i++)
                wmma::load_matrix_sync(a[i], &As[(wm * 64 + i * 16) * LDP + ks * 8], LDP);
            wmma::fragment<wmma::matrix_b, 16, 16, 8, wmma::precision::tf32, wmma::col_major> b[2];
#pragma unroll
            for (int j = 0; j < 2; j++)
                wmma::load_matrix_sync(b[j], &Bs[(wn * 32 + j * 16) * LDP + ks * 8], LDP);
#pragma unroll
            for (int i = 0; i < 4; i++)
#pragma unroll
                for (int j = 0; j < 2; j++)
                    wmma::mma_sync(acc[i][j], a[i], b[j], acc[i][j]);
        }
        __syncthreads();
    }

    // epilogue: stage to smem, add bias + relu, coalesced write
#pragma unroll
    for (int i = 0; i < 4; i++)
#pragma unroll
        for (int j = 0; j < 2; j++)
            wmma::store_matrix_sync(&Cs[(wm * 64 + i * 16) * LDC + wn * 32 + j * 16],
                                    acc[i][j], LDC, wmma::mem_row_major);
    __syncthreads();
    for (int idx = tid; idx < 128 * SZ_IN; idx += 256) {
        const int r   = idx >> 7;
        const int c   = idx & 127;
        const int row = m0 + r;
        if (row < N_NODES) {
            float v = Cs[r * LDC + c] + bias[c];
            g_y[(size_t)row * SZ_IN + c] = v > 0.0f ? v : 0.0f;
        }
    }
}

// ---------------------------------------------------------------------------
// Kernel 2: zero hn
// ---------------------------------------------------------------------------
__global__ void __launch_bounds__(256) zero_hn_kernel() {
    const size_t total4 = (size_t)N_NODES * SZ_IN / 4;
    float4 z = make_float4(0.f, 0.f, 0.f, 0.f);
    for (size_t i = (size_t)blockIdx.x * blockDim.x + threadIdx.x; i < total4;
         i += (size_t)gridDim.x * blockDim.x)
        reinterpret_cast<float4*>(g_hn)[i] = z;
}

// ---------------------------------------------------------------------------
// Kernel 3: scatter-max.  One warp per edge: hn[u] = max(hn[u], y[v]).
// edge_index is INT32. Values >= 0 so int atomicMax on float bits is exact.
// Zero-valued messages are no-ops against the 0-initialized hn -> skip them
// (~50% of post-ReLU values are exactly 0).
// ---------------------------------------------------------------------------
__global__ void __launch_bounds__(256) scatter_max_kernel(
    const int* __restrict__ edge_index, int num_edges)
{
    const int e = (blockIdx.x * blockDim.x + threadIdx.x) >> 5;
    const int lane = threadIdx.x & 31;
    if (e >= num_edges) return;
    const int u = edge_index[e];
    const int v = edge_index[num_edges + e];
    if ((unsigned)u >= N_NODES || (unsigned)v >= N_NODES) return;  // insurance
    const float* src = g_y + (size_t)v * SZ_IN;
    int* dst = reinterpret_cast<int*>(g_hn + (size_t)u * SZ_IN);
#pragma unroll
    for (int j = 0; j < 4; j++) {
        const int f = lane + 32 * j;
        const float val = __ldg(&src[f]);
        if (val > 0.0f) atomicMax(&dst[f], __float_as_int(val));
    }
}

// ---------------------------------------------------------------------------
// Kernel 4: h = relu(concat(x, hn) @ lin_W^T)   [100000 x 1024], K=256
// Tiled: block = 128(M) x 128(N), 8 warps each 64x32, smem-staged A and B.
// K chunks of 32 align with the concat boundary (k<128 from x, else from hn).
// ---------------------------------------------------------------------------
__global__ void __launch_bounds__(256) output_gemm_kernel(
    const float* __restrict__ x,
    const float* __restrict__ lw,    // [1024, 256] row-major (out,in)
    float* __restrict__ out)
{
    __shared__ float As[128 * LDP];
    __shared__ float Bs[128 * LDP];

    const int tid  = threadIdx.x;
    const int warp = tid >> 5;
    const int m0   = blockIdx.x * 128;
    const int n0   = blockIdx.y * 128;
    const int wm   = warp >> 2;   // 0..1
    const int wn   = warp & 3;    // 0..3

    wmma::fragment<wmma::accumulator, 16, 16, 8, float> acc[4][2];
#pragma unroll
    for (int i = 0; i < 4; i++)
#pragma unroll
        for (int j = 0; j < 2; j++) wmma::fill_fragment(acc[i][j], 0.0f);

    for (int kc = 0; kc < 2 * SZ_IN; kc += KC) {
        const float* Abase = (kc < SZ_IN) ? (x + kc) : (g_hn + (kc - SZ_IN));
#pragma unroll
        for (int it = 0; it < 4; it++) {
            const int idx = it * 256 + tid;   // 0..1023
            const int r  = idx >> 3;
            const int kq = idx & 7;
            const int row = m0 + r;
            float4 a = make_float4(0.f, 0.f, 0.f, 0.f);
            if (row < N_NODES)
                a = *reinterpret_cast<const float4*>(Abase + (size_t)row * SZ_IN + kq * 4);
            *reinterpret_cast<float4*>(&As[r * LDP + kq * 4]) = to_tf32x4(a);
            float4 b = *reinterpret_cast<const float4*>(
                lw + (size_t)(n0 + r) * 256 + kc + kq * 4);
            *reinterpret_cast<float4*>(&Bs[r * LDP + kq * 4]) = to_tf32x4(b);
        }
        __syncthreads();
#pragma unroll
        for (int ks = 0; ks < KC / 8; ks++) {
            wmma::fragment<wmma::matrix_a, 16, 16, 8, wmma::precision::tf32, wmma::row_major> a[4];
#pragma unroll
            for (int i = 0; i < 4; i++)
                wmma::load_matrix_sync(a[i], &As[(wm * 64 + i * 16) * LDP + ks * 8], LDP);
            wmma::fragment<wmma::matrix_b, 16, 16, 8, wmma::precision::tf32, wmma::col_major> b[2];
#pragma unroll
            for (int j = 0; j < 2; j++)
                wmma::load_matrix_sync(b[j], &Bs[(wn * 32 + j * 16) * LDP + ks * 8], LDP);
#pragma unroll
            for (int i = 0; i < 4; i++)
#pragma unroll
                for (int j = 0; j < 2; j++)
                    wmma::mma_sync(acc[i][j], a[i], b[j], acc[i][j]);
        }
        __syncthreads();
    }

    // epilogue: relu + direct wmma store (16-row tiles are all-valid or all-OOB
    // since N_NODES % 16 == 0)
#pragma unroll
    for (int i = 0; i < 4; i++) {
        const int mrow = m0 + wm * 64 + i * 16;
        if (mrow + 16 > N_NODES) continue;
#pragma unroll
        for (int j = 0; j < 2; j++) {
#pragma unroll
            for (int e = 0; e < acc[i][j].num_elements; e++)
                acc[i][j].x[e] = fmaxf(acc[i][j].x[e], 0.0f);
            wmma::store_matrix_sync(out + (size_t)mrow * DIM_I + n0 + wn * 32 + j * 16,
                                    acc[i][j], DIM_I, wmma::mem_row_major);
        }
    }
}

// ---------------------------------------------------------------------------
extern "C" void kernel_launch(void* const* d_in, const int* in_sizes, int n_in,
                              void* d_out, int out_size) {
    const float* x     = (const float*)d_in[0];
    const int*   eidx  = (const int*)d_in[1];      // int32 (JAX x64 disabled)
    const float* agg_W = (const float*)d_in[2];
    const float* agg_b = (const float*)d_in[3];
    const float* lin_W = (const float*)d_in[4];
    float*       out   = (float*)d_out;

    const int num_edges = in_sizes[1] / 2;
    const int m_blocks = (N_NODES + 127) / 128;         // 782

    // 1) per-node transform
    node_transform_kernel<<<m_blocks, 256>>>(x, agg_W, agg_b);
    // 2) zero hn
    zero_hn_kernel<<<6400, 256>>>();
    // 3) scatter-max over edges
    {
        const long long total_threads = (long long)num_edges * 32;
        const int blocks = (int)((total_threads + 255) / 256); // 200000
        scatter_max_kernel<<<blocks, 256>>>(eidx, num_edges);
    }
    // 4) output GEMM + relu
    {
        dim3 grid(m_blocks, DIM_I / 128);               // (782, 8)
        output_gemm_kernel<<<grid, 256>>>(x, lin_W, out);
    }
}